// round 1
// baseline (speedup 1.0000x reference)
#include <cuda_runtime.h>
#include <math.h>

#define IMGF 800.0f
#define FS 50
#define NSPAT 2500
#define NA 22500
#define NG 16
#define NR 128

// ---------------- scratch (no allocation allowed) ----------------
__device__ float g_x[512 * NSPAT];        // relu(conv3x3) output [512][2500]
__device__ float g_loc[36 * NSPAT];       // rpn loc head [36][2500]
__device__ float g_cls[18 * NSPAT];       // rpn cls head [18][2500]
__device__ float g_pool[NR * 25088];      // roi pool [128][25088]
__device__ float g_h1[NR * 4096];
__device__ float g_h2[NR * 4096];
__device__ float g_rloc[NR * 84];
__device__ float g_rcls[NR * 21];
__device__ unsigned g_gtmax[NG];          // order-encoded per-gt max IoU
__device__ float g_acc[8];                // loss accumulators

// ---------------- helpers ----------------
__device__ __forceinline__ unsigned f2o(float f) {
    unsigned u = __float_as_uint(f);
    return (u & 0x80000000u) ? ~u : (u | 0x80000000u);
}
__device__ __forceinline__ float o2f(unsigned u) {
    return (u & 0x80000000u) ? __uint_as_float(u & 0x7fffffffu)
                             : __uint_as_float(~u);
}

// IoU with forced-rounding intrinsics so both passes produce identical bits.
__device__ __forceinline__ float iou_one(float ax1, float ay1, float ax2, float ay2,
                                         float bx1, float by1, float bx2, float by2) {
    float tlx = fmaxf(ax1, bx1), tly = fmaxf(ay1, by1);
    float brx = fminf(ax2, bx2), bry = fminf(ay2, by2);
    float w = fmaxf(__fsub_rn(brx, tlx), 0.0f);
    float h = fmaxf(__fsub_rn(bry, tly), 0.0f);
    float inter = __fmul_rn(w, h);
    float aa = __fmul_rn(__fsub_rn(ax2, ax1), __fsub_rn(ay2, ay1));
    float ab = __fmul_rn(__fsub_rn(bx2, bx1), __fsub_rn(by2, by1));
    float den = __fadd_rn(__fsub_rn(__fadd_rn(aa, ab), inter), 1e-9f);
    return __fdiv_rn(inter, den);
}

__device__ __forceinline__ float warp_sum(float v) {
    #pragma unroll
    for (int o = 16; o; o >>= 1) v += __shfl_down_sync(0xffffffffu, v, o);
    return v;
}

// ---------------- init ----------------
__global__ void k_init() {
    int t = threadIdx.x;
    if (t < 8) g_acc[t] = 0.0f;
    if (t < 16) g_gtmax[t] = 0u;
}

// ---------------- 3x3 conv 512->512, SAME pad, + bias + relu ----------------
// Implicit GEMM: M=512 (co), N=2500 (y*50+x), K=4608 (ci*9+dy*3+dx)
__global__ __launch_bounds__(256) void k_conv3(const float* __restrict__ W,
                                               const float* __restrict__ F,
                                               const float* __restrict__ bias) {
    __shared__ __align__(16) float As[16][68];
    __shared__ __align__(16) float Bs[16][64];
    int tid = threadIdx.x;
    int m0 = blockIdx.y * 64;
    int n0 = blockIdx.x * 64;
    int tx = tid & 15, ty = tid >> 4;
    float acc[4][4] = {};
    int la_m = tid >> 2, la_k = (tid & 3) << 2;
    int lb_n = tid & 63, lb_k = tid >> 6;
    int gn = n0 + lb_n;
    bool nok = gn < NSPAT;
    int py = nok ? gn / FS : 0;
    int px = nok ? gn - (gn / FS) * FS : 0;
    const float* Ap = W + (m0 + la_m) * 4608 + la_k;

    for (int kt = 0; kt < 4608; kt += 16) {
        float4 av = *(const float4*)(Ap + kt);
        As[la_k + 0][la_m] = av.x;
        As[la_k + 1][la_m] = av.y;
        As[la_k + 2][la_m] = av.z;
        As[la_k + 3][la_m] = av.w;
        #pragma unroll
        for (int r = 0; r < 4; r++) {
            int k = kt + lb_k + r * 4;
            int ci = k / 9;
            int rr = k - ci * 9;
            int dy = rr / 3;
            int dx = rr - dy * 3;
            int iy = py + dy - 1, ix = px + dx - 1;
            float v = 0.0f;
            if (nok && iy >= 0 && iy < FS && ix >= 0 && ix < FS)
                v = F[ci * NSPAT + iy * FS + ix];
            Bs[lb_k + r * 4][lb_n] = v;
        }
        __syncthreads();
        #pragma unroll
        for (int kk = 0; kk < 16; kk++) {
            float4 a4 = *(const float4*)&As[kk][ty << 2];
            float4 b4 = *(const float4*)&Bs[kk][tx << 2];
            float aa[4] = {a4.x, a4.y, a4.z, a4.w};
            float bb[4] = {b4.x, b4.y, b4.z, b4.w};
            #pragma unroll
            for (int i = 0; i < 4; i++)
                #pragma unroll
                for (int j = 0; j < 4; j++)
                    acc[i][j] += aa[i] * bb[j];
        }
        __syncthreads();
    }
    #pragma unroll
    for (int i = 0; i < 4; i++) {
        int gm = m0 + (ty << 2) + i;
        float bi = bias[gm];
        #pragma unroll
        for (int j = 0; j < 4; j++) {
            int gnn = n0 + (tx << 2) + j;
            if (gnn < NSPAT) g_x[gm * NSPAT + gnn] = fmaxf(acc[i][j] + bi, 0.0f);
        }
    }
}

// ---------------- 1x1 convs (loc 36ch + cls 18ch) ----------------
__global__ void k_conv1(const float* __restrict__ regw, const float* __restrict__ regb,
                        const float* __restrict__ clsw, const float* __restrict__ clsb) {
    __shared__ float wr[512];
    int m = blockIdx.x;  // 0..53
    const float* wsrc = (m < 36) ? (regw + m * 512) : (clsw + (m - 36) * 512);
    float bias = (m < 36) ? regb[m] : clsb[m - 36];
    for (int k = threadIdx.x; k < 512; k += blockDim.x) wr[k] = wsrc[k];
    __syncthreads();
    for (int n = threadIdx.x; n < NSPAT; n += blockDim.x) {
        float s = bias;
        #pragma unroll 8
        for (int k = 0; k < 512; k++) s += wr[k] * g_x[k * NSPAT + n];
        if (m < 36) g_loc[m * NSPAT + n] = s;
        else        g_cls[(m - 36) * NSPAT + n] = s;
    }
}

// ---------------- per-gt max IoU (valid anchors only) ----------------
__global__ void k_ioumax(const float* __restrict__ anchors, const float* __restrict__ bb) {
    __shared__ float sb[64];
    __shared__ unsigned smax[16];
    int tid = threadIdx.x;
    if (tid < 64) sb[tid] = bb[tid];
    if (tid < 16) smax[tid] = 0u;
    __syncthreads();
    int a = blockIdx.x * blockDim.x + tid;
    if (a < NA) {
        float ax1 = anchors[a * 4 + 0], ay1 = anchors[a * 4 + 1];
        float ax2 = anchors[a * 4 + 2], ay2 = anchors[a * 4 + 3];
        bool valid = (ax1 >= 0.0f) && (ay1 >= 0.0f) && (ax2 <= IMGF) && (ay2 <= IMGF);
        if (valid) {
            #pragma unroll
            for (int g = 0; g < NG; g++) {
                float v = iou_one(ax1, ay1, ax2, ay2,
                                  sb[g * 4], sb[g * 4 + 1], sb[g * 4 + 2], sb[g * 4 + 3]);
                atomicMax(&smax[g], f2o(v));
            }
        }
    }
    __syncthreads();
    if (tid < 16) atomicMax(&g_gtmax[tid], smax[tid]);
}

// ---------------- anchor targets + rpn losses ----------------
__global__ void k_rpn_loss(const float* __restrict__ anchors, const float* __restrict__ bb) {
    __shared__ float sb[64];
    __shared__ float sg[16];
    int tid = threadIdx.x;
    if (tid < 64) sb[tid] = bb[tid];
    if (tid >= 64 && tid < 80) sg[tid - 64] = o2f(g_gtmax[tid - 64]);
    __syncthreads();
    int a = blockIdx.x * blockDim.x + tid;
    float s_nll = 0.0f, s_cnt = 0.0f, s_loc = 0.0f, s_pos = 0.0f;
    if (a < NA) {
        float ax1 = anchors[a * 4 + 0], ay1 = anchors[a * 4 + 1];
        float ax2 = anchors[a * 4 + 2], ay2 = anchors[a * 4 + 3];
        bool valid = (ax1 >= 0.0f) && (ay1 >= 0.0f) && (ax2 <= IMGF) && (ay2 <= IMGF);
        float best = -2.0f; int bg = 0; bool match = false;
        #pragma unroll
        for (int g = 0; g < NG; g++) {
            float v = valid ? iou_one(ax1, ay1, ax2, ay2,
                                      sb[g * 4], sb[g * 4 + 1], sb[g * 4 + 2], sb[g * 4 + 3])
                            : -1.0f;
            if (v > best) { best = v; bg = g; }
            if (v == sg[g]) match = true;
        }
        match = match && valid;
        int tc = -1;
        if (valid && best < 0.3f) tc = 0;
        if (valid && best >= 0.7f) tc = 1;
        if (match) tc = 1;
        int n = a / 9;
        int j = a - n * 9;
        if (tc >= 0) {
            float l0 = g_cls[(j * 2 + 0) * NSPAT + n];
            float l1 = g_cls[(j * 2 + 1) * NSPAT + n];
            float mx = fmaxf(l0, l1);
            float lse = mx + logf(expf(l0 - mx) + expf(l1 - mx));
            s_nll = lse - (tc ? l1 : l0);
            s_cnt = 1.0f;
        }
        if (tc == 1) {
            float bx1 = sb[bg * 4], by1 = sb[bg * 4 + 1];
            float bx2 = sb[bg * 4 + 2], by2 = sb[bg * 4 + 3];
            float aw = ax2 - ax1, ah = ay2 - ay1;
            float axc = ax1 + aw * 0.5f, ayc = ay1 + ah * 0.5f;
            float gw = bx2 - bx1, gh = by2 - by1;
            float gxc = bx1 + gw * 0.5f, gyc = by1 + gh * 0.5f;
            float t[4];
            t[0] = (gxc - axc) / aw;
            t[1] = (gyc - ayc) / ah;
            t[2] = logf(gw / aw + 1e-9f);
            t[3] = logf(gh / ah + 1e-9f);
            #pragma unroll
            for (int d = 0; d < 4; d++) {
                float pl = g_loc[(j * 4 + d) * NSPAT + n];
                float x = fabsf(t[d] - pl);
                s_loc += (x < 0.5f ? 0.5f * x * x : 0.0f) + (x > 0.5f ? x - 0.5f : 0.0f);
            }
            s_pos = 1.0f;
        }
    }
    s_nll = warp_sum(s_nll);
    s_cnt = warp_sum(s_cnt);
    s_loc = warp_sum(s_loc);
    s_pos = warp_sum(s_pos);
    if ((tid & 31) == 0) {
        atomicAdd(&g_acc[0], s_nll);
        atomicAdd(&g_acc[1], s_cnt);
        atomicAdd(&g_acc[2], s_loc);
        atomicAdd(&g_acc[3], s_pos);
    }
}

// ---------------- roi max pool (7x7 bins, 2x2 samples) ----------------
__global__ void k_roipool(const float* __restrict__ feat, const float* __restrict__ rois) {
    int r = blockIdx.x;
    __shared__ int six[7][2], siy[7][2];
    int t = threadIdx.x;
    float x1 = rois[r * 4 + 0] * 0.0625f, y1 = rois[r * 4 + 1] * 0.0625f;
    float x2 = rois[r * 4 + 2] * 0.0625f, y2 = rois[r * 4 + 3] * 0.0625f;
    if (t < 14) {
        int i = t >> 1, s = t & 1;
        float fr = (i + 0.25f + 0.5f * s) / 7.0f;
        int ix = (int)floorf(x1 + fr * (x2 - x1));
        six[i][s] = min(max(ix, 0), FS - 1);
    } else if (t < 28) {
        int u = t - 14;
        int i = u >> 1, s = u & 1;
        float fr = (i + 0.25f + 0.5f * s) / 7.0f;
        int iy = (int)floorf(y1 + fr * (y2 - y1));
        siy[i][s] = min(max(iy, 0), FS - 1);
    }
    __syncthreads();
    for (int idx = t; idx < 25088; idx += blockDim.x) {
        int c = idx / 49;
        int b = idx - c * 49;
        int i = b / 7;
        int j = b - i * 7;
        const float* fc = feat + c * NSPAT;
        int ya = siy[i][0] * FS, yb = siy[i][1] * FS;
        int xa = six[j][0], xb = six[j][1];
        float v = fmaxf(fmaxf(fc[ya + xa], fc[ya + xb]), fmaxf(fc[yb + xa], fc[yb + xb]));
        g_pool[r * 25088 + idx] = v;
    }
}

// ---------------- generic fp32 GEMM: C[M,N] = A[M,K] @ B[K,N] + bias[N] ----------------
template <int RELU>
__global__ __launch_bounds__(256) void k_gemm(const float* __restrict__ A,
                                              const float* __restrict__ B,
                                              const float* __restrict__ bias,
                                              float* __restrict__ C, int N, int K) {
    __shared__ __align__(16) float As[16][68];
    __shared__ __align__(16) float Bs[16][64];
    int tid = threadIdx.x;
    int m0 = blockIdx.y * 64;
    int n0 = blockIdx.x * 64;
    int tx = tid & 15, ty = tid >> 4;
    float acc[4][4] = {};
    int la_m = tid >> 2, la_k = (tid & 3) << 2;
    int lb_n = tid & 63, lb_k = tid >> 6;
    int gbn = n0 + lb_n;
    bool nok = gbn < N;
    const float* Ap = A + (m0 + la_m) * K + la_k;

    for (int kt = 0; kt < K; kt += 16) {
        float4 av = *(const float4*)(Ap + kt);
        As[la_k + 0][la_m] = av.x;
        As[la_k + 1][la_m] = av.y;
        As[la_k + 2][la_m] = av.z;
        As[la_k + 3][la_m] = av.w;
        #pragma unroll
        for (int r = 0; r < 4; r++) {
            int k = lb_k + r * 4;
            Bs[k][lb_n] = nok ? B[(kt + k) * N + gbn] : 0.0f;
        }
        __syncthreads();
        #pragma unroll
        for (int kk = 0; kk < 16; kk++) {
            float4 a4 = *(const float4*)&As[kk][ty << 2];
            float4 b4 = *(const float4*)&Bs[kk][tx << 2];
            float aa[4] = {a4.x, a4.y, a4.z, a4.w};
            float bb[4] = {b4.x, b4.y, b4.z, b4.w};
            #pragma unroll
            for (int i = 0; i < 4; i++)
                #pragma unroll
                for (int j = 0; j < 4; j++)
                    acc[i][j] += aa[i] * bb[j];
        }
        __syncthreads();
    }
    #pragma unroll
    for (int i = 0; i < 4; i++) {
        int gm = m0 + (ty << 2) + i;
        #pragma unroll
        for (int j = 0; j < 4; j++) {
            int gnn = n0 + (tx << 2) + j;
            if (gnn < N) {
                float v = acc[i][j] + bias[gnn];
                if (RELU) v = fmaxf(v, 0.0f);
                C[gm * N + gnn] = v;
            }
        }
    }
}

// ---------------- roi losses ----------------
__global__ void k_roiloss(const float* __restrict__ gt_loc, const int* __restrict__ labels) {
    int r = threadIdx.x;  // 128 threads
    float nll = 0.0f, lloss = 0.0f, pos = 0.0f;
    {
        const float* lg = g_rcls + r * 21;
        float mx = lg[0];
        #pragma unroll
        for (int c = 1; c < 21; c++) mx = fmaxf(mx, lg[c]);
        float se = 0.0f;
        #pragma unroll
        for (int c = 0; c < 21; c++) se += expf(lg[c] - mx);
        int lab = labels[r];
        nll = mx + logf(se) - lg[lab];
        if (lab > 0) {
            pos = 1.0f;
            #pragma unroll
            for (int d = 0; d < 4; d++) {
                float x = fabsf(g_rloc[r * 84 + lab * 4 + d] - gt_loc[r * 4 + d]);
                lloss += (x < 0.5f ? 0.5f * x * x : 0.0f) + (x > 0.5f ? x - 0.5f : 0.0f);
            }
        }
    }
    nll = warp_sum(nll);
    lloss = warp_sum(lloss);
    pos = warp_sum(pos);
    if ((r & 31) == 0) {
        atomicAdd(&g_acc[4], nll);
        atomicAdd(&g_acc[5], lloss);
        atomicAdd(&g_acc[6], pos);
    }
}

// ---------------- final combine ----------------
__global__ void k_final(float* __restrict__ out) {
    float rpn_cls = g_acc[0] / fmaxf(g_acc[1], 1.0f);
    float rpn_loc = g_acc[2];
    float t_rpn = rpn_cls + (10.0f / fmaxf(g_acc[3], 1.0f)) * rpn_loc;
    float roi_cls = g_acc[4] / 128.0f;
    float roi_loc = g_acc[5];
    float t_roi = roi_cls + (10.0f / fmaxf(g_acc[6], 1.0f)) * roi_loc;
    out[0] = rpn_cls;
    out[1] = rpn_loc;
    out[2] = roi_cls;
    out[3] = roi_loc;
    out[4] = t_roi + t_rpn;
}

// ---------------- launcher ----------------
extern "C" void kernel_launch(void* const* d_in, const int* in_sizes, int n_in,
                              void* d_out, int out_size) {
    (void)in_sizes; (void)n_in; (void)out_size;
    const float* feat    = (const float*)d_in[0];
    const float* bboxes  = (const float*)d_in[1];
    const float* rois    = (const float*)d_in[2];
    const float* gt_loc  = (const float*)d_in[3];
    const float* anchors = (const float*)d_in[4];
    const float* rpn_w   = (const float*)d_in[5];
    const float* rpn_b   = (const float*)d_in[6];
    const float* reg_w   = (const float*)d_in[7];
    const float* reg_b   = (const float*)d_in[8];
    const float* cls_w   = (const float*)d_in[9];
    const float* cls_b   = (const float*)d_in[10];
    const float* fc1_w   = (const float*)d_in[11];
    const float* fc1_b   = (const float*)d_in[12];
    const float* fc2_w   = (const float*)d_in[13];
    const float* fc2_b   = (const float*)d_in[14];
    const float* hr_w    = (const float*)d_in[15];
    const float* hr_b    = (const float*)d_in[16];
    const float* hc_w    = (const float*)d_in[17];
    const float* hc_b    = (const float*)d_in[18];
    const int*   labels  = (const int*)d_in[19];
    float* out = (float*)d_out;

    void *p_pool, *p_h1, *p_h2, *p_rloc, *p_rcls;
    cudaGetSymbolAddress(&p_pool, g_pool);
    cudaGetSymbolAddress(&p_h1, g_h1);
    cudaGetSymbolAddress(&p_h2, g_h2);
    cudaGetSymbolAddress(&p_rloc, g_rloc);
    cudaGetSymbolAddress(&p_rcls, g_rcls);

    k_init<<<1, 32>>>();
    k_conv3<<<dim3(40, 8), 256>>>(rpn_w, feat, rpn_b);
    k_conv1<<<54, 256>>>(reg_w, reg_b, cls_w, cls_b);
    k_ioumax<<<88, 256>>>(anchors, bboxes);
    k_rpn_loss<<<88, 256>>>(anchors, bboxes);
    k_roipool<<<128, 256>>>(feat, rois);
    k_gemm<1><<<dim3(64, 2), 256>>>((const float*)p_pool, fc1_w, fc1_b, (float*)p_h1, 4096, 25088);
    k_gemm<1><<<dim3(64, 2), 256>>>((const float*)p_h1, fc2_w, fc2_b, (float*)p_h2, 4096, 4096);
    k_gemm<0><<<dim3(2, 2), 256>>>((const float*)p_h2, hr_w, hr_b, (float*)p_rloc, 84, 4096);
    k_gemm<0><<<dim3(1, 2), 256>>>((const float*)p_h2, hc_w, hc_b, (float*)p_rcls, 21, 4096);
    k_roiloss<<<1, 128>>>(gt_loc, labels);
    k_final<<<1, 1>>>(out);
}